// round 11
// baseline (speedup 1.0000x reference)
#include <cuda_runtime.h>
#include <cuda_bf16.h>
#include <cstdint>

// ---------------------------------------------------------------------------
// RelativeMultiHeadAttn (Transformer-XL style) forward.
//
// qkv = x @ Wqkv via tcgen05 bf16 split-precision GEMM (K concat trick):
//   A2 = [Xhi | Xlo | Xhi]  (4096 x 3072 bf16, K-major)
//   B2 = [Whi | Whi | Wlo]^T (3072 x 3072 bf16, K-major)
//   qkv = A2 @ B2^T  accumulated fp32 in TMEM  ==  x@W up to ~2^-18 residual.
// tcgen05 / f32x2 bodies guarded for the sm_103a arch-specific pass; the
// plain compute_103 pass compiles scalar fp32 fallbacks.
//
// score: 64x64 tiles, blocked 4x4/thread, f32x2 FMAs packed over d-pairs
// (all operands natural 64-bit units; zero pack instructions). Band trick:
//   BD_shift[i,j] = (q_i + r_w) . R[:, L + j - i]
//   E_term[i,j]   = k_j . R[:, L + i - j]
// av: softmax + PV with packed f32x2 FMAs over d-pairs.
// ---------------------------------------------------------------------------

namespace {
constexpr int BATCH = 8;
constexpr int NH    = 16;
constexpr int SEQ   = 512;
constexpr int DM    = 1024;
constexpr int HD    = 64;
constexpr int P2    = 2 * SEQ;      // 1024
constexpr int BH    = BATCH * NH;   // 128
constexpr int QKV_N = 3 * DM;       // 3072
constexpr int MROWS = BATCH * SEQ;  // 4096
constexpr int KTOT  = 3 * DM;       // 3072 (split-K concat)
constexpr int CH    = 64;           // K chunk (one SW128 atom column of bf16)
constexpr int NCH   = KTOT / CH;    // 48
}

// scratch (static device globals: allowed; no dynamic allocation)
__device__ float         g_qkv[(size_t)MROWS * QKV_N];    // 50 MB fp32
__device__ __nv_bfloat16 g_A2[(size_t)MROWS * KTOT];      // 25 MB
__device__ __nv_bfloat16 g_B2[(size_t)QKV_N * KTOT];      // 19 MB

// Feature gate: true only in the sm_103a (arch-specific) device pass.
#ifndef __CUDA_ARCH_SPECIFIC__
#define __CUDA_ARCH_SPECIFIC__ 0
#endif
#if !defined(__CUDA_ARCH__) || defined(__CUDA_ARCH_FEAT_SM103_ALL) || \
    (__CUDA_ARCH_SPECIFIC__ == 1030)
#define HAS_TCGEN05 1
#else
#define HAS_TCGEN05 0
#endif

typedef unsigned long long ull;

// packed fp32x2 FMA: d.lo += a.lo*b.lo ; d.hi += a.hi*b.hi
#if HAS_TCGEN05
__device__ __forceinline__ void ffma2(ull& d, ull a, ull b) {
  asm("fma.rn.f32x2 %0, %1, %2, %0;" : "+l"(d) : "l"(a), "l"(b));
}
#else
__device__ __forceinline__ void ffma2(ull& d, ull a, ull b) {
  float dl = __uint_as_float((uint32_t)d),  dh = __uint_as_float((uint32_t)(d >> 32));
  float al = __uint_as_float((uint32_t)a),  ah = __uint_as_float((uint32_t)(a >> 32));
  float bl = __uint_as_float((uint32_t)b),  bh = __uint_as_float((uint32_t)(b >> 32));
  dl = fmaf(al, bl, dl);
  dh = fmaf(ah, bh, dh);
  d = (ull)__float_as_uint(dl) | ((ull)__float_as_uint(dh) << 32);
}
#endif

// ===========================================================================
// minimal sm_103a PTX helpers
// ===========================================================================
__device__ __forceinline__ uint32_t smem_u32(const void* p) {
  uint32_t a;
  asm("{ .reg .u64 t; cvta.to.shared.u64 t, %1; cvt.u32.u64 %0, t; }"
      : "=r"(a) : "l"(p));
  return a;
}
#if HAS_TCGEN05
__device__ __forceinline__ uint32_t elect_one() {
  uint32_t pred;
  asm volatile("{\n\t.reg .pred p;\n\telect.sync _|p, 0xFFFFFFFF;\n\t"
               "selp.b32 %0, 1, 0, p;\n\t}" : "=r"(pred));
  return pred;
}
__device__ __forceinline__ void mbar_init(uint32_t mbar, uint32_t cnt) {
  asm volatile("mbarrier.init.shared.b64 [%0], %1;" :: "r"(mbar), "r"(cnt) : "memory");
}
__device__ __forceinline__ void mbar_wait(uint32_t mbar, uint32_t parity) {
  asm volatile(
      "{\n\t.reg .pred P;\n\t"
      "WL_%=:\n\t"
      "mbarrier.try_wait.parity.acquire.cta.shared::cta.b64 P, [%0], %1, 0x989680;\n\t"
      "@P bra.uni WD_%=;\n\t"
      "bra.uni WL_%=;\n\t"
      "WD_%=:\n\t}"
      :: "r"(mbar), "r"(parity) : "memory");
}
__device__ __forceinline__ void tmem_alloc(uint32_t smem_dst, uint32_t ncols) {
  asm volatile("tcgen05.alloc.cta_group::1.sync.aligned.shared::cta.b32 [%0], %1;"
               :: "r"(smem_dst), "r"(ncols) : "memory");
}
__device__ __forceinline__ void tmem_relinq() {
  asm volatile("tcgen05.relinquish_alloc_permit.cta_group::1.sync.aligned;");
}
__device__ __forceinline__ void tmem_dealloc(uint32_t tmem, uint32_t ncols) {
  asm volatile("tcgen05.dealloc.cta_group::1.sync.aligned.b32 %0, %1;"
               :: "r"(tmem), "r"(ncols));
}
__device__ __forceinline__ void tcommit(uint32_t mbar) {
  asm volatile(
      "tcgen05.commit.cta_group::1.mbarrier::arrive::one.shared::cluster.b64 [%0];"
      :: "r"(mbar) : "memory");
}
__device__ __forceinline__ void fence_async_shared() {
  asm volatile("fence.proxy.async.shared::cta;" ::: "memory");
}
__device__ __forceinline__ void tfence_after() {
  asm volatile("tcgen05.fence::after_thread_sync;" ::: "memory");
}
__device__ __forceinline__ void mma_f16_ss(uint32_t d, uint64_t ad, uint64_t bd,
                                           uint32_t idesc, uint32_t en) {
  asm volatile(
      "{\n\t.reg .pred p;\n\tsetp.ne.u32 p, %5, 0;\n\t"
      "tcgen05.mma.cta_group::1.kind::f16 [%0], %1, %2, %3, {%4, %4, %4, %4}, p;\n\t}"
      :: "r"(d), "l"(ad), "l"(bd), "r"(idesc), "r"(0u), "r"(en) : "memory");
}
#define TC_LD_X32(r, addr)                                                      \
  asm volatile(                                                                 \
      "tcgen05.ld.sync.aligned.32x32b.x32.b32 "                                 \
      "{%0,%1,%2,%3,%4,%5,%6,%7,%8,%9,%10,%11,%12,%13,%14,%15,"                \
      "%16,%17,%18,%19,%20,%21,%22,%23,%24,%25,%26,%27,%28,%29,%30,%31}, [%32];" \
      : "=r"((r)[0]), "=r"((r)[1]), "=r"((r)[2]), "=r"((r)[3]),                 \
        "=r"((r)[4]), "=r"((r)[5]), "=r"((r)[6]), "=r"((r)[7]),                 \
        "=r"((r)[8]), "=r"((r)[9]), "=r"((r)[10]), "=r"((r)[11]),               \
        "=r"((r)[12]), "=r"((r)[13]), "=r"((r)[14]), "=r"((r)[15]),             \
        "=r"((r)[16]), "=r"((r)[17]), "=r"((r)[18]), "=r"((r)[19]),             \
        "=r"((r)[20]), "=r"((r)[21]), "=r"((r)[22]), "=r"((r)[23]),             \
        "=r"((r)[24]), "=r"((r)[25]), "=r"((r)[26]), "=r"((r)[27]),             \
        "=r"((r)[28]), "=r"((r)[29]), "=r"((r)[30]), "=r"((r)[31])              \
      : "r"(addr))
__device__ __forceinline__ void tc_wait_ld() {
  asm volatile("tcgen05.wait::ld.sync.aligned;" ::: "memory");
}
// SW128 K-major SMEM descriptor (LBO=1, SBO=64, version=1, layout=2)
__device__ __forceinline__ uint64_t smem_desc_sw128(uint32_t addr) {
  const uint64_t base = (uint64_t(2) << 61) | (uint64_t(1) << 46) |
                        (uint64_t(64) << 32) | (uint64_t(1) << 16);
  return base | ((uint64_t)(addr >> 4) & 0x3FFF);
}
#endif  // HAS_TCGEN05

// idesc: fp32 accum, bf16 x bf16, M=128, N=128
namespace {
constexpr uint32_t IDESC =
    (1u << 4) | (1u << 7) | (1u << 10) | ((128u / 8) << 17) | ((128u / 16) << 24);
}

// ===========================================================================
// Conversion kernels: fp32 -> split bf16 (hi/lo), B transposed to K-major
// ===========================================================================
__global__ __launch_bounds__(256) void k_convA(const float* __restrict__ X) {
  size_t i = (size_t)blockIdx.x * 256 + threadIdx.x;  // quad index
  float4 v = ((const float4*)X)[i];
  size_t m = i >> 8;
  size_t q = (i & 255) * 4;

  __nv_bfloat162 h01 = __floats2bfloat162_rn(v.x, v.y);
  __nv_bfloat162 h23 = __floats2bfloat162_rn(v.z, v.w);
  float lx = v.x - __bfloat162float(h01.x);
  float ly = v.y - __bfloat162float(h01.y);
  float lz = v.z - __bfloat162float(h23.x);
  float lw = v.w - __bfloat162float(h23.y);
  __nv_bfloat162 l01 = __floats2bfloat162_rn(lx, ly);
  __nv_bfloat162 l23 = __floats2bfloat162_rn(lz, lw);

  uint2 uh, ul;
  uh.x = *(uint32_t*)&h01; uh.y = *(uint32_t*)&h23;
  ul.x = *(uint32_t*)&l01; ul.y = *(uint32_t*)&l23;

  __nv_bfloat16* row = g_A2 + m * KTOT;
  *(uint2*)(row + q)          = uh;
  *(uint2*)(row + DM + q)     = ul;
  *(uint2*)(row + 2 * DM + q) = uh;
}

__global__ __launch_bounds__(256) void k_convB(const float* __restrict__ W) {
  __shared__ float tile[32][33];
  const int n0 = blockIdx.x * 32;
  const int k0 = blockIdx.y * 32;
  const int tid = threadIdx.x;
#pragma unroll
  for (int it = 0; it < 4; it++) {
    int e = tid + it * 256;
    int kk = e >> 5, nn = e & 31;
    tile[kk][nn] = W[(size_t)(k0 + kk) * QKV_N + n0 + nn];
  }
  __syncthreads();
#pragma unroll
  for (int it = 0; it < 4; it++) {
    int e = tid + it * 256;
    int nn = e >> 5, kk = e & 31;
    float x = tile[kk][nn];
    __nv_bfloat16 hi = __float2bfloat16_rn(x);
    __nv_bfloat16 lo = __float2bfloat16_rn(x - __bfloat162float(hi));
    __nv_bfloat16* row = g_B2 + (size_t)(n0 + nn) * KTOT;
    row[k0 + kk]          = hi;
    row[DM + k0 + kk]     = hi;
    row[2 * DM + k0 + kk] = lo;
  }
}

// ===========================================================================
// Kernel: qkv = A2 @ B2^T via tcgen05 (unchanged from round 7)
// ===========================================================================
namespace {
constexpr int QSMEM = 1024 + 4 * 16384;
}

__global__ __launch_bounds__(256) void k_qkv_mma(const float* __restrict__ X,
                                                 const float* __restrict__ W) {
#if HAS_TCGEN05
  extern __shared__ char smem[];
  const uint32_t sb = smem_u32(smem);
  const uint32_t TPTR  = sb;
  const uint32_t MBAR0 = sb + 16;
  const uint32_t MBAR1 = sb + 24;
  const uint32_t STAGE = sb + 1024;

  const int tid = threadIdx.x;
  const int wid = tid >> 5;

  if (wid == 0) tmem_alloc(TPTR, 128);
  if (tid == 0) { mbar_init(MBAR0, 1); mbar_init(MBAR1, 1); }
  __syncthreads();
  uint32_t tmem;
  asm volatile("ld.shared.b32 %0, [%1];" : "=r"(tmem) : "r"(TPTR));
  if (wid == 0) tmem_relinq();

  const int m0 = blockIdx.y * 128;
  const int n0 = blockIdx.x * 128;
  const __nv_bfloat16* Ag = g_A2 + (size_t)m0 * KTOT;
  const __nv_bfloat16* Bg = g_B2 + (size_t)n0 * KTOT;

  const int row = tid >> 1;
  const int sg0 = (tid & 1) * 4;

  uint32_t ph0 = 0, ph1 = 0;
  for (int t = 0; t < NCH; t++) {
    const int p = t & 1;
    const uint32_t Abase = STAGE + p * 32768;
    const uint32_t Bbase = Abase + 16384;
    if (t >= 2) {
      if (p == 0) { mbar_wait(MBAR0, ph0); ph0 ^= 1; }
      else        { mbar_wait(MBAR1, ph1); ph1 ^= 1; }
    }
    const int kc = t * CH;
    uint4 av[4], bv[4];
    const char* arow = (const char*)(Ag + (size_t)row * KTOT + kc);
    const char* brow = (const char*)(Bg + (size_t)row * KTOT + kc);
#pragma unroll
    for (int s = 0; s < 4; s++) {
      av[s] = *(const uint4*)(arow + (sg0 + s) * 16);
      bv[s] = *(const uint4*)(brow + (sg0 + s) * 16);
    }
#pragma unroll
    for (int s = 0; s < 4; s++) {
      uint32_t off = row * 128 + (sg0 + s) * 16;
      uint32_t sw = off ^ ((off >> 3) & 0x70);
      *(uint4*)(smem + (Abase - sb) + sw) = av[s];
      *(uint4*)(smem + (Bbase - sb) + sw) = bv[s];
    }
    __syncthreads();
    if (wid == 0) {
      if (elect_one()) {
        fence_async_shared();
        uint64_t ad = smem_desc_sw128(Abase);
        uint64_t bd = smem_desc_sw128(Bbase);
#pragma unroll
        for (int k = 0; k < 4; k++)
          mma_f16_ss(tmem, ad + k * 2, bd + k * 2, IDESC, (t > 0 || k > 0) ? 1u : 0u);
        tcommit(p == 0 ? MBAR0 : MBAR1);
      }
    }
  }
  mbar_wait(MBAR1, ph1);
  tfence_after();

  if (wid < 4) {
    const int lid = tid & 31;
    const int orow = m0 + wid * 32 + lid;
#pragma unroll
    for (int cb = 0; cb < 128; cb += 32) {
      uint32_t d[32];
      TC_LD_X32(d, tmem + cb);
      tc_wait_ld();
      float* dst = g_qkv + (size_t)orow * QKV_N + n0 + cb;
#pragma unroll
      for (int c = 0; c < 32; c += 4)
        *(float4*)(dst + c) = make_float4(__uint_as_float(d[c]),
                                          __uint_as_float(d[c + 1]),
                                          __uint_as_float(d[c + 2]),
                                          __uint_as_float(d[c + 3]));
    }
  }
  __syncthreads();
  if (wid == 0) tmem_dealloc(tmem, 128);

#else  // ------------- FFMA fallback (non-sm_103a pass; still correct) -------
  extern __shared__ char smemraw[];
  float* sA = (float*)smemraw;
  float* sB = sA + 16 * 128;
  const int K = DM, N = QKV_N;
  const int tid = threadIdx.x;
  const int tx = tid & 15, ty = tid >> 4;
  const int row0 = blockIdx.y * 128;
  const int col0 = blockIdx.x * 128;

  float acc[8][8];
#pragma unroll
  for (int r = 0; r < 8; r++)
#pragma unroll
    for (int c = 0; c < 8; c++) acc[r][c] = 0.f;

  for (int kk = 0; kk < K; kk += 16) {
#pragma unroll
    for (int it = 0; it < 2; it++) {
      int e = tid + it * 256;
      int ar = e >> 2;
      int ac = (e & 3) * 4;
      float4 a4 = *(const float4*)(X + (size_t)(row0 + ar) * K + kk + ac);
      sA[(ac + 0) * 128 + ar] = a4.x;
      sA[(ac + 1) * 128 + ar] = a4.y;
      sA[(ac + 2) * 128 + ar] = a4.z;
      sA[(ac + 3) * 128 + ar] = a4.w;
    }
#pragma unroll
    for (int it = 0; it < 2; it++) {
      int e = tid + it * 256;
      int br = e >> 5;
      int bc = (e & 31) * 4;
      *(float4*)&sB[br * 128 + bc] = *(const float4*)(W + (size_t)(kk + br) * N + col0 + bc);
    }
    __syncthreads();
#pragma unroll
    for (int k = 0; k < 16; k++) {
      float ar[8], bc[8];
      *(float4*)&ar[0] = *(float4*)&sA[k * 128 + ty * 8];
      *(float4*)&ar[4] = *(float4*)&sA[k * 128 + ty * 8 + 4];
      *(float4*)&bc[0] = *(float4*)&sB[k * 128 + tx * 8];
      *(float4*)&bc[4] = *(float4*)&sB[k * 128 + tx * 8 + 4];
#pragma unroll
      for (int r = 0; r < 8; r++)
#pragma unroll
        for (int c = 0; c < 8; c++) acc[r][c] += ar[r] * bc[c];
    }
    __syncthreads();
  }
#pragma unroll
  for (int r = 0; r < 8; r++) {
    float* dst = g_qkv + (size_t)(row0 + ty * 8 + r) * QKV_N + col0 + tx * 8;
    *(float4*)dst       = make_float4(acc[r][0], acc[r][1], acc[r][2], acc[r][3]);
    *(float4*)(dst + 4) = make_float4(acc[r][4], acc[r][5], acc[r][6], acc[r][7]);
  }
#endif
}

// ===========================================================================
// Kernel: fused score. 64x64 tile, 256 threads, blocked 4x4 per thread,
// f32x2 FMAs packed over d-pairs (zero pack instructions).
//   sQ : [64 r][64 d] row-major          (a2 reads are lane-broadcast LDS.64)
//   sK : [32 dp][64 c][2] d-interleaved  (b2 reads stride-8B, conflict-free)
//   sRq/sRe : [DPH dp][128 x][2] chunks  (pair reads via aligned 16B LDS)
// attn_score = (AC + BD + E)/8 + prev -> prev_out
// ===========================================================================
namespace {
constexpr int DPH     = 8;   // d-pairs per band chunk (16 d)
constexpr int SC_SMEM = (4096 + 4096 + 2 * DPH * 256) * 4;  // 49152 B
}

__global__ __launch_bounds__(256, 2) void k_score(const float* __restrict__ rrb,
                                                  const float* __restrict__ rwb,
                                                  const float* __restrict__ relpos,
                                                  const float* __restrict__ prev,
                                                  const int* __restrict__ skip,
                                                  float* __restrict__ prev_out) {
  extern __shared__ float smemf[];
  float* sQ  = smemf;             // [64 r][64 d]
  float* sK  = sQ + 4096;         // [32 dp][64 c][2]
  float* sRq = sK + 4096;         // [DPH][128][2]
  float* sRe = sRq + DPH * 256;   // [DPH][128][2]
  __shared__ float cK[64];        // rrb . k_j
  __shared__ float cRq[128];      // rwb . R_t (127 used), accumulated per chunk

  const int bh = blockIdx.z;
  const int b = bh >> 4, h = bh & 15;
  const int tid = threadIdx.x;
  const int tx = tid & 15, ty = tid >> 4;
  const int i0 = blockIdx.y * 64;
  const int j0 = blockIdx.x * 64;

  const float* Qb = g_qkv + (size_t)(b * SEQ) * QKV_N + h * HD;
  const float* Kb = Qb + DM;

  // sQ fill: straight row-major copy (coalesced LDG, conflict-free STS)
#pragma unroll
  for (int it = 0; it < 4; it++) {
    int e = tid + it * 256;       // 64 rows x 16 float4
    int r = e >> 4;
    int c = (e & 15) * 4;
    *(float4*)&sQ[r * 64 + c] = *(const float4*)(Qb + (size_t)(i0 + r) * QKV_N + c);
  }
  // sK fill d-interleaved: lanes over c -> conflict-free STS.64 (LDG strided,
  // sector-granular; fill is tiny vs main loop)
#pragma unroll
  for (int it = 0; it < 4; it++) {
    int e = tid + it * 256;       // 1024 tasks: c = e&63, d4 = (e>>6)*4
    int cc = e & 63;
    int d4 = (e >> 6) * 4;
    float4 k4 = *(const float4*)(Kb + (size_t)(j0 + cc) * QKV_N + d4);
    int dp0 = d4 >> 1;
    *(float2*)&sK[dp0 * 128 + cc * 2]       = make_float2(k4.x, k4.y);
    *(float2*)&sK[(dp0 + 1) * 128 + cc * 2] = make_float2(k4.z, k4.w);
  }
  if (tid < 128) cRq[tid] = 0.f;
  __syncthreads();

  // rank-1 correction cK (full-K sK available)
  if (tid < 64) {
    float s = 0.f;
#pragma unroll
    for (int dp = 0; dp < 32; dp++) {
      float2 kv = *(float2*)&sK[dp * 128 + tid * 2];
      s += rrb[h * HD + 2 * dp] * kv.x + rrb[h * HD + 2 * dp + 1] * kv.y;
    }
    cK[tid] = s;
  }

  ull acc2[4][4];
#pragma unroll
  for (int r = 0; r < 4; r++)
#pragma unroll
    for (int c = 0; c < 4; c++) acc2[r][c] = 0ull;

  // blocked tile: rows i0 + ty*4 + r, cols j0 + tx*4 + c
  const int rqb = 4 * (tx - ty) + 60;   // band base (x index), in [0, 120]
  const int reb = 4 * (ty - tx) + 60;
  const int q0g = SEQ + (j0 - i0) - 63; // global band starts, within [1,1023]
  const int u0g = SEQ + (i0 - j0) - 63;

  for (int chk = 0; chk < 4; chk++) {
    const int d0 = chk * 2 * DPH;       // base d for this chunk (16 d)
    // fill band chunks, d-pair interleaved (lanes over x: conflict-free)
    for (int e = tid; e < DPH * 128; e += 256) {
      int p = e >> 7, x = e & 127;
      if (x < 127) {
        int d = d0 + 2 * p;
        *(float2*)&sRq[(p * 128 + x) * 2] =
            make_float2(relpos[(size_t)d * P2 + q0g + x],
                        relpos[(size_t)(d + 1) * P2 + q0g + x]);
        *(float2*)&sRe[(p * 128 + x) * 2] =
            make_float2(relpos[(size_t)d * P2 + u0g + x],
                        relpos[(size_t)(d + 1) * P2 + u0g + x]);
      }
    }
    __syncthreads();

    // accumulate cRq partial for this chunk
    if (tid < 127) {
      float s = 0.f;
#pragma unroll
      for (int p = 0; p < DPH; p++) {
        float2 v = *(float2*)&sRq[(p * 128 + tid) * 2];
        s += rwb[h * HD + d0 + 2 * p] * v.x + rwb[h * HD + d0 + 2 * p + 1] * v.y;
      }
      cRq[tid] += s;
    }

#pragma unroll
    for (int pl = 0; pl < DPH; pl++) {
      const int dp = chk * DPH + pl;    // global d-pair index 0..31
      ull a2[4], b2[4], t2[8];
#pragma unroll
      for (int j = 0; j < 4; j++)
        a2[j] = *(const ull*)&sQ[(ty * 4 + j) * 64 + 2 * dp];
#pragma unroll
      for (int j = 0; j < 4; j++)
        b2[j] = *(const ull*)&sK[dp * 128 + (tx * 4 + j) * 2];

      // main term: AC
#pragma unroll
      for (int r = 0; r < 4; r++)
#pragma unroll
        for (int c = 0; c < 4; c++) ffma2(acc2[r][c], a2[r], b2[c]);

      // BD term: band pairs t2[k] = {Rq[d][rqb+k], Rq[d+1][rqb+k]}
      {
        const float* base = &sRq[pl * 256 + 2 * rqb];
#pragma unroll
        for (int m = 0; m < 4; m++) {
          ulonglong2 v = *(const ulonglong2*)(base + 4 * m);
          t2[2 * m] = v.x; t2[2 * m + 1] = v.y;
        }
      }
#pragma unroll
      for (int r = 0; r < 4; r++)
#pragma unroll
        for (int c = 0; c < 4; c++) ffma2(acc2[r][c], a2[r], t2[c - r + 3]);

      // E term: reuse t2 with the mirrored band
      {
        const float* base = &sRe[pl * 256 + 2 * reb];
#pragma unroll
        for (int m = 0; m < 4; m++) {
          ulonglong2 v = *(const ulonglong2*)(base + 4 * m);
          t2[2 * m] = v.x; t2[2 * m + 1] = v.y;
        }
      }
#pragma unroll
      for (int r = 0; r < 4; r++)
#pragma unroll
        for (int c = 0; c < 4; c++) ffma2(acc2[r][c], b2[c], t2[r - c + 3]);
    }
    __syncthreads();
  }

  const int sk = *skip;
  const float* prevb = prev + (size_t)bh * SEQ * SEQ;
  float* outb = prev_out + (size_t)bh * SEQ * SEQ;

#pragma unroll
  for (int r = 0; r < 4; r++) {
    const int i = i0 + ty * 4 + r;
    const int j = j0 + tx * 4;
    float4 p = make_float4(0.f, 0.f, 0.f, 0.f);
    if (sk) p = *(const float4*)(prevb + (size_t)i * SEQ + j);
    float4 o;
#pragma unroll
    for (int c = 0; c < 4; c++) {
      float lo = __uint_as_float((uint32_t)(acc2[r][c] & 0xffffffffull));
      float hi = __uint_as_float((uint32_t)(acc2[r][c] >> 32));
      float s = (lo + hi) + cK[tx * 4 + c] + cRq[rqb + c - r + 3];
      ((float*)&o)[c] = s * 0.125f;   // 1/sqrt(64)
    }
    o.x += p.x; o.y += p.y; o.z += p.z; o.w += p.w;
    *(float4*)(outb + (size_t)i * SEQ + j) = o;
  }
}

// ===========================================================================
// Kernel: out = softmax(S) @ V. 64 rows/block, 4x4 tile.
// sm_103a path: packed f32x2 FMAs over d-pairs, V stored d-interleaved.
// (unchanged from round 10)
// ===========================================================================
namespace {
constexpr int ROWS_AV   = 64;
constexpr int SS_STRIDE = 516;
constexpr int SMEM_AV   = (ROWS_AV * SS_STRIDE + 64 * 64) * 4;  // 148480 B
}

__global__ __launch_bounds__(256) void k_av(const float* __restrict__ Sglob,
                                            float* __restrict__ Out) {
  extern __shared__ float smemf[];
  float* sS = smemf;
  float* sV = smemf + ROWS_AV * SS_STRIDE;   // f32x2 path: [32 kp][64 c][2]
  __shared__ float sSum[ROWS_AV];

  const int bh = blockIdx.y;
  const int b = bh >> 4, h = bh & 15;
  const int row0 = blockIdx.x * ROWS_AV;
  const int tid = threadIdx.x;
  const int tx = tid & 15, ty = tid >> 4;
  const float* Sb = Sglob + ((size_t)bh * SEQ + row0) * SEQ;

#pragma unroll
  for (int it = 0; it < 32; it++) {
    int e = tid + it * 256;
    int r = e >> 7;
    int c = (e & 127) * 4;
    *(float4*)&sS[r * SS_STRIDE + c] = *(const float4*)(Sb + (size_t)r * SEQ + c);
  }
  __syncthreads();

  {
    const int warp = tid >> 5, lane = tid & 31;
#pragma unroll
    for (int rr = 0; rr < 8; rr++) {
      int row = warp * 8 + rr;
      float* srow = sS + row * SS_STRIDE;
      float mx = -1e30f;
      for (int c = lane; c < SEQ; c += 32) mx = fmaxf(mx, srow[c]);
#pragma unroll
      for (int o = 16; o > 0; o >>= 1) mx = fmaxf(mx, __shfl_xor_sync(0xffffffffu, mx, o));
      float sum = 0.f;
      for (int c = lane; c < SEQ; c += 32) {
        float p = __expf(srow[c] - mx);
        srow[c] = p;
        sum += p;
      }
#pragma unroll
      for (int o = 16; o > 0; o >>= 1) sum += __shfl_xor_sync(0xffffffffu, sum, o);
      if (lane == 0) sSum[row] = sum;
    }
  }

  const float* Vb = g_qkv + (size_t)(b * SEQ) * QKV_N + 2 * DM + h * HD;

#if HAS_TCGEN05
  // ---- packed f32x2 PV: accumulate even-d in lane0, odd-d in lane1 ----
  ull acc2[4][4];
#pragma unroll
  for (int r = 0; r < 4; r++)
#pragma unroll
    for (int c = 0; c < 4; c++) acc2[r][c] = 0ull;

  for (int kc = 0; kc < SEQ; kc += 64) {
    __syncthreads();
    // fill V interleaved: sV[kp*128 + 2c + par] = V[kc + 2kp + par][c]
#pragma unroll
    for (int it = 0; it < 8; it++) {
      int e = tid + it * 256;     // 2048 tasks: kp = e>>6, c = e&63
      int kp = e >> 6;
      int c  = e & 63;
      float v0 = Vb[(size_t)(kc + 2 * kp) * QKV_N + c];
      float v1 = Vb[(size_t)(kc + 2 * kp + 1) * QKV_N + c];
      *(float2*)&sV[kp * 128 + 2 * c] = make_float2(v0, v1);
    }
    __syncthreads();
#pragma unroll 8
    for (int kp = 0; kp < 32; kp++) {
      ull p2[4], v2[4];
#pragma unroll
      for (int r = 0; r < 4; r++)
        p2[r] = *(const ull*)&sS[(ty + 16 * r) * SS_STRIDE + kc + 2 * kp];
#pragma unroll
      for (int c = 0; c < 4; c++)
        v2[c] = *(const ull*)&sV[kp * 128 + (tx + 16 * c) * 2];
#pragma unroll
      for (int r = 0; r < 4; r++)
#pragma unroll
        for (int c = 0; c < 4; c++) ffma2(acc2[r][c], p2[r], v2[c]);
    }
  }

#pragma unroll
  for (int r = 0; r < 4; r++) {
    const float inv = 1.f / sSum[ty + 16 * r];
    float* dst = Out + ((size_t)b * SEQ + row0 + ty + 16 * r) * DM + h * HD + tx;
#pragma unroll
    for (int c = 0; c < 4; c++) {
      float lo = __uint_as_float((uint32_t)(acc2[r][c] & 0xffffffffull));
      float hi = __uint_as_float((uint32_t)(acc2[r][c] >> 32));
      dst[16 * c] = (lo + hi) * inv;
    }
  }

#else
  // ---- scalar fallback (non-sm_103a pass) ----
  float acc[4][4];
#pragma unroll
  for (int r = 0; r < 4; r++)
#pragma unroll
    for (int c = 0; c < 4; c++) acc[r][c] = 0.f;

  for (int kc = 0; kc < SEQ; kc += 64) {
    __syncthreads();
#pragma unroll
    for (int it = 0; it < 4; it++) {
      int e = tid + it * 256;
      int kk = e >> 4;
      int c = (e & 15) * 4;
      *(float4*)&sV[kk * 64 + c] = *(const float4*)(Vb + (size_t)(kc + kk) * QKV_N + c);
    }
    __syncthreads();
#pragma unroll 8
    for (int kk = 0; kk < 64; kk++) {
      float p[4], v[4];
#pragma unroll
      for (int r = 0; r < 4; r++) p[r] = sS[(ty + 16 * r) * SS_STRIDE + kc + kk];
#pragma unroll
      for (int c = 0; c < 4; c++) v[c] = sV[kk * 64 + tx + 16 * c];
#pragma unroll
      for (int r = 0; r < 4; r++)
#pragma unroll
        for (int c = 0; c < 4; c++) acc[r][c] += p[r] * v[c];
    }
  }

#pragma unroll
  for (int r = 0; r < 4; r++) {
    const float inv = 1.f / sSum[ty + 16 * r];
    float* dst = Out + ((size_t)b * SEQ + row0 + ty + 16 * r) * DM + h * HD + tx;
#pragma unroll
    for (int c = 0; c < 4; c++) dst[16 * c] = acc[r][c] * inv;
  }
#endif
}

// ---------------------------------------------------------------------------
extern "C" void kernel_launch(void* const* d_in, const int* in_sizes, int n_in,
                              void* d_out, int out_size) {
  const float* x      = (const float*)d_in[0];
  const float* prev   = (const float*)d_in[1];
  const float* Wqkv   = (const float*)d_in[2];
  const float* rrb    = (const float*)d_in[3];
  const float* rwb    = (const float*)d_in[4];
  const float* relpos = (const float*)d_in[5];
  const int*   skip   = (const int*)d_in[6];

  float* out      = (float*)d_out;                       // (8,512,1024)
  float* prev_out = out + (size_t)BATCH * SEQ * DM;      // (8,16,512,512)

  k_convA<<<(MROWS * DM / 4) / 256, 256>>>(x);
  k_convB<<<dim3(QKV_N / 32, DM / 32), 256>>>(Wqkv);

  cudaFuncSetAttribute(k_qkv_mma, cudaFuncAttributeMaxDynamicSharedMemorySize, QSMEM);
  k_qkv_mma<<<dim3(QKV_N / 128, MROWS / 128), 256, QSMEM>>>(x, Wqkv);

  cudaFuncSetAttribute(k_score, cudaFuncAttributeMaxDynamicSharedMemorySize, SC_SMEM);
  dim3 g3(SEQ / 64, SEQ / 64, BH);                       // (8, 8, 128)
  k_score<<<g3, 256, SC_SMEM>>>(rrb, rwb, relpos, prev, skip, prev_out);

  cudaFuncSetAttribute(k_av, cudaFuncAttributeMaxDynamicSharedMemorySize, SMEM_AV);
  dim3 g4(SEQ / ROWS_AV, BH);                            // (8, 128)
  k_av<<<g4, 256, SMEM_AV>>>(prev_out, out);
}